// round 1
// baseline (speedup 1.0000x reference)
#include <cuda_runtime.h>
#include <math.h>
#include <math_constants.h>

#define BB 8
#define SS 2500
#define EE 128
#define FF 128
#define LL 8921

// ---------------- device scratch (no allocations allowed) ----------------
__device__ __align__(16) float g_wp3[3 * EE * FF];
__device__ __align__(16) float g_wp5[5 * EE * FF];
__device__ __align__(16) float g_wp9[9 * EE * FF];
__device__ __align__(16) float g_wf[(size_t)BB * FF * SS];   // word_features [B][F][S]
__device__ float g_y_fb[BB * LL];                            // fallback targets if the
__device__ float g_ctx_fb[(size_t)BB * LL * FF];             // output layout differs

// ---------------- weight repack: [F][E][K] -> [K][E][F] ----------------
__global__ void repack_kernel(const float* __restrict__ src,
                              float* __restrict__ dst, int K) {
    int idx = blockIdx.x * blockDim.x + threadIdx.x;
    int total = K * EE * FF;
    if (idx >= total) return;
    int kk = idx / (EE * FF);
    int r  = idx % (EE * FF);
    int e  = r / FF;
    int f  = r % FF;
    dst[idx] = src[(f * EE + e) * K + kk];
}

// ---------------- conv helper: one kernel size, max-accumulate ----------------
template <int K>
__device__ __forceinline__ void conv_max(const float* __restrict__ wp,
                                         const float* __restrict__ bias,
                                         const float (*xs)[40],
                                         int f0, int sb, float mx[4][4]) {
    float acc[4][4];
#pragma unroll
    for (int i = 0; i < 4; i++)
#pragma unroll
        for (int j = 0; j < 4; j++) acc[i][j] = 0.f;

    const int P = K / 2;
#pragma unroll 1
    for (int kk = 0; kk < K; kk++) {
        const float* wr = wp + kk * (EE * FF) + f0;
        const int base = sb + kk - P;
#pragma unroll 4
        for (int e = 0; e < EE; e++) {
            float4 wv = *(const float4*)(wr + e * FF);
            float x0 = xs[e][base + 0];
            float x1 = xs[e][base + 1];
            float x2 = xs[e][base + 2];
            float x3 = xs[e][base + 3];
            acc[0][0] += wv.x * x0; acc[0][1] += wv.x * x1;
            acc[0][2] += wv.x * x2; acc[0][3] += wv.x * x3;
            acc[1][0] += wv.y * x0; acc[1][1] += wv.y * x1;
            acc[1][2] += wv.y * x2; acc[1][3] += wv.y * x3;
            acc[2][0] += wv.z * x0; acc[2][1] += wv.z * x1;
            acc[2][2] += wv.z * x2; acc[2][3] += wv.z * x3;
            acc[3][0] += wv.w * x0; acc[3][1] += wv.w * x1;
            acc[3][2] += wv.w * x2; acc[3][3] += wv.w * x3;
        }
    }
#pragma unroll
    for (int i = 0; i < 4; i++) {
        float bi = bias[f0 + i];
#pragma unroll
        for (int j = 0; j < 4; j++)
            mx[i][j] = fmaxf(mx[i][j], tanhf(acc[i][j] + bi));
    }
}

// ---------------- fused embed-gather + 3x conv + tanh + max ----------------
// grid: (ceil(S/32), B), block: 256. Each thread computes 4f x 4s outputs.
__global__ __launch_bounds__(256) void conv_kernel(
    const int* __restrict__ docs, const float* __restrict__ embed,
    const float* __restrict__ b3, const float* __restrict__ b5,
    const float* __restrict__ b9) {
    __shared__ float xs[EE][40];  // positions s0-4 .. s0+35

    int b  = blockIdx.y;
    int s0 = blockIdx.x * 32;
    int tid = threadIdx.x, w = tid >> 5, lane = tid & 31;

    // gather embedding rows (warp w handles 5 positions)
#pragma unroll
    for (int q = 0; q < 5; q++) {
        int p = w * 5 + q;
        int s = s0 - 4 + p;
        if (s >= 0 && s < SS) {
            int tok = docs[b * SS + s];
            const float* er = embed + (size_t)tok * EE;
            xs[lane      ][p] = er[lane];
            xs[lane + 32][p] = er[lane + 32];
            xs[lane + 64][p] = er[lane + 64];
            xs[lane + 96][p] = er[lane + 96];
        } else {
            xs[lane][p] = 0.f; xs[lane + 32][p] = 0.f;
            xs[lane + 64][p] = 0.f; xs[lane + 96][p] = 0.f;
        }
    }
    __syncthreads();

    int fg = tid >> 3;       // 0..31 -> f = 4*fg
    int sg = tid & 7;        // 0..7  -> s = s0 + 4*sg
    int f0 = fg * 4;
    int sb = 4 + sg * 4;     // xs index of si=0

    float mx[4][4];
#pragma unroll
    for (int i = 0; i < 4; i++)
#pragma unroll
        for (int j = 0; j < 4; j++) mx[i][j] = -1e30f;

    conv_max<3>(g_wp3, b3, xs, f0, sb, mx);
    conv_max<5>(g_wp5, b5, xs, f0, sb, mx);
    conv_max<9>(g_wp9, b9, xs, f0, sb, mx);

#pragma unroll
    for (int i = 0; i < 4; i++) {
        float* orow = g_wf + ((size_t)b * FF + f0 + i) * SS;
#pragma unroll
        for (int j = 0; j < 4; j++) {
            int s = s0 + sg * 4 + j;
            if (s < SS) orow[s] = mx[i][j];
        }
    }
}

// ---------------- fused label attention (online softmax) + y ----------------
// grid: (ceil(L/32), B), block 256 (8 warps). Warp w owns labels {w, w+8, w+16, w+24}
// within the 32-label block tile. Lane = key position within the 32-wide S tile.
__global__ __launch_bounds__(256) void attn_kernel(
    const float* __restrict__ wu_w, const int* __restrict__ leaf,
    const float* __restrict__ fw, const float* __restrict__ fb,
    float* __restrict__ y_out, float* __restrict__ ctx_out) {
    __shared__ __align__(16) float s_wu[32][128];
    __shared__ __align__(16) float s_x[32][132];  // s-major; 132 stride = conflict-free f4
    __shared__ float s_p[32][33];

    int b   = blockIdx.y;
    int l0  = blockIdx.x * 32;
    int tid = threadIdx.x, w = tid >> 5, lane = tid & 31;

    for (int q = tid; q < 32 * 128; q += 256) {
        int li = q >> 7, f = q & 127;
        int gl = l0 + li;
        s_wu[li][f] = (gl < LL) ? wu_w[(size_t)leaf[gl] * FF + f] : 0.f;
    }

    float m_[4], se[4], cx[4][4];
#pragma unroll
    for (int i = 0; i < 4; i++) {
        m_[i] = -CUDART_INF_F;
        se[i] = 0.f;
#pragma unroll
        for (int j = 0; j < 4; j++) cx[i][j] = 0.f;
    }

    const float* wfb = g_wf + (size_t)b * FF * SS;
    const int l_[4] = {w, w + 8, w + 16, w + 24};

    for (int s0 = 0; s0 < SS; s0 += 32) {
        __syncthreads();
        // load tile: s_x[j][f] = wf[b][f][s0+j]
        for (int q = tid; q < 4096; q += 256) {
            int f = q >> 5, j = q & 31;
            int s = s0 + j;
            s_x[j][f] = (s < SS) ? wfb[f * SS + s] : 0.f;
        }
        __syncthreads();

        // scores: lane computes score(l_i, s0+lane)
        float acc[4] = {0.f, 0.f, 0.f, 0.f};
        const float4* xr = (const float4*)(&s_x[lane][0]);
#pragma unroll 8
        for (int fq = 0; fq < 32; fq++) {
            float4 xv = xr[fq];
#pragma unroll
            for (int i = 0; i < 4; i++) {
                float4 uv = *(const float4*)(&s_wu[l_[i]][fq * 4]);
                acc[i] += uv.x * xv.x + uv.y * xv.y + uv.z * xv.z + uv.w * xv.w;
            }
        }
        bool valid = (s0 + lane) < SS;

        // online softmax update per owned label
#pragma unroll
        for (int i = 0; i < 4; i++) {
            float a = valid ? acc[i] : -CUDART_INF_F;
            float tm = a;
#pragma unroll
            for (int o = 16; o; o >>= 1)
                tm = fmaxf(tm, __shfl_xor_sync(0xffffffffu, tm, o));
            float mn = fmaxf(m_[i], tm);
            float sc = __expf(m_[i] - mn);
            float p  = valid ? __expf(a - mn) : 0.f;
            float ts = p;
#pragma unroll
            for (int o = 16; o; o >>= 1)
                ts += __shfl_xor_sync(0xffffffffu, ts, o);
            se[i] = se[i] * sc + ts;
            m_[i] = mn;
#pragma unroll
            for (int j = 0; j < 4; j++) cx[i][j] *= sc;
            s_p[l_[i]][lane] = p;
        }
        __syncwarp();

        // context accumulation: cx[i][j] covers (label l_i, feature lane+32j)
#pragma unroll 4
        for (int s = 0; s < 32; s++) {
            float x0 = s_x[s][lane];
            float x1 = s_x[s][lane + 32];
            float x2 = s_x[s][lane + 64];
            float x3 = s_x[s][lane + 96];
#pragma unroll
            for (int i = 0; i < 4; i++) {
                float pv = s_p[l_[i]][s];
                cx[i][0] += pv * x0; cx[i][1] += pv * x1;
                cx[i][2] += pv * x2; cx[i][3] += pv * x3;
            }
        }
    }

    // epilogue: normalize, write context, reduce y
#pragma unroll
    for (int i = 0; i < 4; i++) {
        int gl = l0 + l_[i];
        if (gl >= LL) continue;
        float inv = 1.0f / se[i];
        float yacc = 0.f;
        size_t base = ((size_t)b * LL + gl) * FF;
#pragma unroll
        for (int j = 0; j < 4; j++) {
            int f = lane + 32 * j;
            float c = cx[i][j] * inv;
            ctx_out[base + f] = c;
            yacc += c * fw[(size_t)gl * FF + f];
        }
#pragma unroll
        for (int o = 16; o; o >>= 1)
            yacc += __shfl_xor_sync(0xffffffffu, yacc, o);
        if (lane == 0) y_out[(size_t)b * LL + gl] = yacc + fb[gl];
    }
}

// ---------------- launch ----------------
extern "C" void kernel_launch(void* const* d_in, const int* in_sizes, int n_in,
                              void* d_out, int out_size) {
    const int*   docs  = (const int*)  d_in[0];
    // d_in[1] doc_masks, d_in[2] doc_lengths: unused by the reference math
    const int*   leaf  = (const int*)  d_in[3];
    const float* embed = (const float*)d_in[4];
    const float* wu    = (const float*)d_in[5];
    const float* fw    = (const float*)d_in[6];
    const float* fb    = (const float*)d_in[7];
    const float* w3    = (const float*)d_in[8];
    const float* b3    = (const float*)d_in[9];
    const float* w5    = (const float*)d_in[10];
    const float* b5    = (const float*)d_in[11];
    const float* w9    = (const float*)d_in[12];
    const float* b9    = (const float*)d_in[13];

    const long long NY = (long long)BB * LL;
    const long long NC = (long long)BB * LL * FF;
    float* out = (float*)d_out;
    float* d_y;
    float* d_ctx;
    if ((long long)out_size == NY + NC) {        // (y, context) concatenated
        d_y = out; d_ctx = out + NY;
    } else if ((long long)out_size == NC) {      // context only
        d_ctx = out;
        cudaGetSymbolAddress((void**)&d_y, g_y_fb);
    } else if ((long long)out_size == NY) {      // y only
        d_y = out;
        cudaGetSymbolAddress((void**)&d_ctx, g_ctx_fb);
    } else {                                     // assume (y, context)
        d_y = out; d_ctx = out + NY;
    }

    float* wp3; float* wp5; float* wp9;
    cudaGetSymbolAddress((void**)&wp3, g_wp3);
    cudaGetSymbolAddress((void**)&wp5, g_wp5);
    cudaGetSymbolAddress((void**)&wp9, g_wp9);

    repack_kernel<<<(3 * EE * FF + 255) / 256, 256>>>(w3, wp3, 3);
    repack_kernel<<<(5 * EE * FF + 255) / 256, 256>>>(w5, wp5, 5);
    repack_kernel<<<(9 * EE * FF + 255) / 256, 256>>>(w9, wp9, 9);

    dim3 cgrid((SS + 31) / 32, BB);
    conv_kernel<<<cgrid, 256>>>(docs, embed, b3, b5, b9);

    dim3 agrid((LL + 31) / 32, BB);
    attn_kernel<<<agrid, 256>>>(wu, leaf, fw, fb, d_y, d_ctx);
}

// round 4
// speedup vs baseline: 2.5665x; 2.5665x over previous
#include <cuda_runtime.h>
#include <math.h>
#include <math_constants.h>
#include <stdint.h>

#define BB 8
#define SS 2500
#define EE 128
#define FF 128
#define LL 8921

// ---------------- device scratch (no allocations allowed) ----------------
__device__ __align__(16) float g_wp3[3 * EE * FF];
__device__ __align__(16) float g_wp5[5 * EE * FF];
__device__ __align__(16) float g_wp9[9 * EE * FF];
__device__ __align__(16) float g_wf[(size_t)BB * FF * SS];   // word_features [B][F][S]
__device__ float g_y_fb[BB * LL];
__device__ float g_ctx_fb[(size_t)BB * LL * FF];

// ---------------- weight repack: [F][E][K] -> [K][E][F] ----------------
__global__ void repack_kernel(const float* __restrict__ src,
                              float* __restrict__ dst, int K) {
    int idx = blockIdx.x * blockDim.x + threadIdx.x;
    int total = K * EE * FF;
    if (idx >= total) return;
    int kk = idx / (EE * FF);
    int r  = idx % (EE * FF);
    int e  = r / FF;
    int f  = r % FF;
    dst[idx] = src[(f * EE + e) * K + kk];
}

// ---------------- conv helper: one kernel size, max-accumulate ----------------
template <int K>
__device__ __forceinline__ void conv_max(const float* __restrict__ wp,
                                         const float* __restrict__ bias,
                                         const float (*xs)[40],
                                         int f0, int sb, float mx[4][4]) {
    float acc[4][4];
#pragma unroll
    for (int i = 0; i < 4; i++)
#pragma unroll
        for (int j = 0; j < 4; j++) acc[i][j] = 0.f;

    const int P = K / 2;
#pragma unroll 1
    for (int kk = 0; kk < K; kk++) {
        const float* wr = wp + kk * (EE * FF) + f0;
        const int base = sb + kk - P;
#pragma unroll 4
        for (int e = 0; e < EE; e++) {
            float4 wv = *(const float4*)(wr + e * FF);
            float x0 = xs[e][base + 0];
            float x1 = xs[e][base + 1];
            float x2 = xs[e][base + 2];
            float x3 = xs[e][base + 3];
            acc[0][0] += wv.x * x0; acc[0][1] += wv.x * x1;
            acc[0][2] += wv.x * x2; acc[0][3] += wv.x * x3;
            acc[1][0] += wv.y * x0; acc[1][1] += wv.y * x1;
            acc[1][2] += wv.y * x2; acc[1][3] += wv.y * x3;
            acc[2][0] += wv.z * x0; acc[2][1] += wv.z * x1;
            acc[2][2] += wv.z * x2; acc[2][3] += wv.z * x3;
            acc[3][0] += wv.w * x0; acc[3][1] += wv.w * x1;
            acc[3][2] += wv.w * x2; acc[3][3] += wv.w * x3;
        }
    }
#pragma unroll
    for (int i = 0; i < 4; i++) {
        float bi = bias[f0 + i];
#pragma unroll
        for (int j = 0; j < 4; j++)
            mx[i][j] = fmaxf(mx[i][j], tanhf(acc[i][j] + bi));
    }
}

// ---------------- fused embed-gather + 3x conv + tanh + max ----------------
__global__ __launch_bounds__(256) void conv_kernel(
    const int* __restrict__ docs, const float* __restrict__ embed,
    const float* __restrict__ b3, const float* __restrict__ b5,
    const float* __restrict__ b9) {
    __shared__ float xs[EE][40];

    int b  = blockIdx.y;
    int s0 = blockIdx.x * 32;
    int tid = threadIdx.x, w = tid >> 5, lane = tid & 31;

#pragma unroll
    for (int q = 0; q < 5; q++) {
        int p = w * 5 + q;
        int s = s0 - 4 + p;
        if (s >= 0 && s < SS) {
            int tok = docs[b * SS + s];
            const float* er = embed + (size_t)tok * EE;
            xs[lane      ][p] = er[lane];
            xs[lane + 32][p] = er[lane + 32];
            xs[lane + 64][p] = er[lane + 64];
            xs[lane + 96][p] = er[lane + 96];
        } else {
            xs[lane][p] = 0.f; xs[lane + 32][p] = 0.f;
            xs[lane + 64][p] = 0.f; xs[lane + 96][p] = 0.f;
        }
    }
    __syncthreads();

    int fg = tid >> 3;
    int sg = tid & 7;
    int f0 = fg * 4;
    int sb = 4 + sg * 4;

    float mx[4][4];
#pragma unroll
    for (int i = 0; i < 4; i++)
#pragma unroll
        for (int j = 0; j < 4; j++) mx[i][j] = -1e30f;

    conv_max<3>(g_wp3, b3, xs, f0, sb, mx);
    conv_max<5>(g_wp5, b5, xs, f0, sb, mx);
    conv_max<9>(g_wp9, b9, xs, f0, sb, mx);

#pragma unroll
    for (int i = 0; i < 4; i++) {
        float* orow = g_wf + ((size_t)b * FF + f0 + i) * SS;
#pragma unroll
        for (int j = 0; j < 4; j++) {
            int s = s0 + sg * 4 + j;
            if (s < SS) orow[s] = mx[i][j];
        }
    }
}

// ================= tensor-core label attention =================
// block = 128 threads (4 warps). Each warp owns 16 labels, runs the full
// online-softmax flash loop over S independently (no cross-warp reduction).
// GEMM1: scores[16l x 32s] = WU[16 x 128] @ X[128 x 32]   (tf32 mma)
// GEMM2: ctx[16l x 128f]  += P[16 x 32] @ X^T[32 x 128]   (tf32 mma)

#define LBLK 64
#define WU_STRIDE 132
#define X_STRIDE  36
#define P_STRIDE  36

__device__ __forceinline__ uint32_t f2tf32(float v) {
    uint32_t t;
    asm("cvt.rna.tf32.f32 %0, %1;" : "=r"(t) : "f"(v));
    return t;
}

__device__ __forceinline__ void mma_tf32(float (&d)[4],
                                         uint32_t a0, uint32_t a1,
                                         uint32_t a2, uint32_t a3,
                                         uint32_t b0, uint32_t b1) {
    asm volatile(
        "mma.sync.aligned.m16n8k8.row.col.f32.tf32.tf32.f32 "
        "{%0,%1,%2,%3}, {%4,%5,%6,%7}, {%8,%9}, {%0,%1,%2,%3};"
        : "+f"(d[0]), "+f"(d[1]), "+f"(d[2]), "+f"(d[3])
        : "r"(a0), "r"(a1), "r"(a2), "r"(a3), "r"(b0), "r"(b1));
}

__global__ __launch_bounds__(128) void attn_tc_kernel(
    const float* __restrict__ wu_w, const int* __restrict__ leaf,
    const float* __restrict__ fw, const float* __restrict__ fb,
    float* __restrict__ y_out, float* __restrict__ ctx_out) {
    extern __shared__ float sm[];
    float* s_wu = sm;                              // [64][132]
    float* s_x  = sm + LBLK * WU_STRIDE;           // [128][36]
    float* s_p  = s_x + FF * X_STRIDE;             // [4][16][36]

    int b   = blockIdx.y;
    int l0  = blockIdx.x * LBLK;
    int tid = threadIdx.x;
    int wid = tid >> 5, lane = tid & 31;
    int q = lane & 3;        // thread-in-group (k/col group)
    int r = lane >> 2;       // group id (row)

    // stage WU once (tf32-rounded)
    for (int idx = tid; idx < LBLK * FF; idx += 128) {
        int li = idx >> 7, f = idx & 127;
        int gl = l0 + li;
        float v = (gl < LL) ? wu_w[(size_t)leaf[gl] * FF + f] : 0.f;
        s_wu[li * WU_STRIDE + f] = __uint_as_float(f2tf32(v));
    }

    const float* wfb = g_wf + (size_t)b * FF * SS;
    float* s_pw = s_p + wid * 16 * P_STRIDE;
    const int lrow = 16 * wid + r;     // warp's m-tile rows: lrow, lrow+8 (local)

    float ctx[16][4];
#pragma unroll
    for (int nt = 0; nt < 16; nt++)
#pragma unroll
        for (int c = 0; c < 4; c++) ctx[nt][c] = 0.f;

    float m0 = -CUDART_INF_F, m1 = -CUDART_INF_F;
    float se0 = 0.f, se1 = 0.f;

    for (int s0 = 0; s0 < SS; s0 += 32) {
        __syncthreads();
        // load X tile [f][s], tf32-rounded
        for (int idx = tid; idx < FF * 32; idx += 128) {
            int f = idx >> 5, j = idx & 31;
            int s = s0 + j;
            float v = (s < SS) ? wfb[(size_t)f * SS + s] : 0.f;
            s_x[f * X_STRIDE + j] = __uint_as_float(f2tf32(v));
        }
        __syncthreads();

        // ---- GEMM1: scores ----
        float sc[4][4];
#pragma unroll
        for (int nt = 0; nt < 4; nt++)
#pragma unroll
            for (int c = 0; c < 4; c++) sc[nt][c] = 0.f;

#pragma unroll 4
        for (int k = 0; k < 16; k++) {
            int k0 = 8 * k;
            uint32_t a0 = __float_as_uint(s_wu[lrow * WU_STRIDE + k0 + q]);
            uint32_t a1 = __float_as_uint(s_wu[(lrow + 8) * WU_STRIDE + k0 + q]);
            uint32_t a2 = __float_as_uint(s_wu[lrow * WU_STRIDE + k0 + q + 4]);
            uint32_t a3 = __float_as_uint(s_wu[(lrow + 8) * WU_STRIDE + k0 + q + 4]);
#pragma unroll
            for (int nt = 0; nt < 4; nt++) {
                uint32_t b0 = __float_as_uint(s_x[(k0 + q) * X_STRIDE + 8 * nt + r]);
                uint32_t b1 = __float_as_uint(s_x[(k0 + q + 4) * X_STRIDE + 8 * nt + r]);
                mma_tf32(sc[nt], a0, a1, a2, a3, b0, b1);
            }
        }

        // ---- mask tail columns ----
#pragma unroll
        for (int nt = 0; nt < 4; nt++) {
            int s_even = s0 + 8 * nt + 2 * q;
            if (s_even >= SS)     { sc[nt][0] = -CUDART_INF_F; sc[nt][2] = -CUDART_INF_F; }
            if (s_even + 1 >= SS) { sc[nt][1] = -CUDART_INF_F; sc[nt][3] = -CUDART_INF_F; }
        }

        // ---- online softmax (per-row, within 4-lane group) ----
        float mx0 = -CUDART_INF_F, mx1 = -CUDART_INF_F;
#pragma unroll
        for (int nt = 0; nt < 4; nt++) {
            mx0 = fmaxf(mx0, fmaxf(sc[nt][0], sc[nt][1]));
            mx1 = fmaxf(mx1, fmaxf(sc[nt][2], sc[nt][3]));
        }
        mx0 = fmaxf(mx0, __shfl_xor_sync(0xffffffffu, mx0, 1));
        mx0 = fmaxf(mx0, __shfl_xor_sync(0xffffffffu, mx0, 2));
        mx1 = fmaxf(mx1, __shfl_xor_sync(0xffffffffu, mx1, 1));
        mx1 = fmaxf(mx1, __shfl_xor_sync(0xffffffffu, mx1, 2));

        float nm0 = fmaxf(m0, mx0), nm1 = fmaxf(m1, mx1);
        float scale0 = __expf(m0 - nm0), scale1 = __expf(m1 - nm1);
        m0 = nm0; m1 = nm1;

        float sum0 = 0.f, sum1 = 0.f;
#pragma unroll
        for (int nt = 0; nt < 4; nt++) {
            float p0 = __expf(sc[nt][0] - m0);
            float p1 = __expf(sc[nt][1] - m0);
            float p2 = __expf(sc[nt][2] - m1);
            float p3 = __expf(sc[nt][3] - m1);
            sum0 += p0 + p1;
            sum1 += p2 + p3;
            int col = 8 * nt + 2 * q;
            s_pw[r * P_STRIDE + col]           = __uint_as_float(f2tf32(p0));
            s_pw[r * P_STRIDE + col + 1]       = __uint_as_float(f2tf32(p1));
            s_pw[(r + 8) * P_STRIDE + col]     = __uint_as_float(f2tf32(p2));
            s_pw[(r + 8) * P_STRIDE + col + 1] = __uint_as_float(f2tf32(p3));
        }
        sum0 += __shfl_xor_sync(0xffffffffu, sum0, 1);
        sum0 += __shfl_xor_sync(0xffffffffu, sum0, 2);
        sum1 += __shfl_xor_sync(0xffffffffu, sum1, 1);
        sum1 += __shfl_xor_sync(0xffffffffu, sum1, 2);
        se0 = se0 * scale0 + sum0;
        se1 = se1 * scale1 + sum1;

        // rescale running context
#pragma unroll
        for (int nt = 0; nt < 16; nt++) {
            ctx[nt][0] *= scale0; ctx[nt][1] *= scale0;
            ctx[nt][2] *= scale1; ctx[nt][3] *= scale1;
        }
        __syncwarp();

        // ---- GEMM2: ctx += P @ X^T ----
#pragma unroll
        for (int k = 0; k < 4; k++) {
            int k0 = 8 * k;
            uint32_t a0 = __float_as_uint(s_pw[r * P_STRIDE + k0 + q]);
            uint32_t a1 = __float_as_uint(s_pw[(r + 8) * P_STRIDE + k0 + q]);
            uint32_t a2 = __float_as_uint(s_pw[r * P_STRIDE + k0 + q + 4]);
            uint32_t a3 = __float_as_uint(s_pw[(r + 8) * P_STRIDE + k0 + q + 4]);
#pragma unroll
            for (int nt = 0; nt < 16; nt++) {
                uint32_t b0 = __float_as_uint(s_x[(8 * nt + r) * X_STRIDE + k0 + q]);
                uint32_t b1 = __float_as_uint(s_x[(8 * nt + r) * X_STRIDE + k0 + q + 4]);
                mma_tf32(ctx[nt], a0, a1, a2, a3, b0, b1);
            }
        }
        __syncwarp();
    }

    // ---- epilogue: normalize, write context, fused y ----
    float inv0 = 1.f / se0, inv1 = 1.f / se1;
    int gl0 = l0 + lrow, gl1 = gl0 + 8;
    bool v0 = gl0 < LL, v1 = gl1 < LL;
    size_t cb0 = ((size_t)b * LL + gl0) * FF;
    size_t cb1 = ((size_t)b * LL + gl1) * FF;
    float y0 = 0.f, y1 = 0.f;
#pragma unroll
    for (int nt = 0; nt < 16; nt++) {
        int f = 8 * nt + 2 * q;
        if (v0) {
            float c0 = ctx[nt][0] * inv0, c1 = ctx[nt][1] * inv0;
            float2 fwv = *(const float2*)(fw + (size_t)gl0 * FF + f);
            *(float2*)(ctx_out + cb0 + f) = make_float2(c0, c1);
            y0 += c0 * fwv.x + c1 * fwv.y;
        }
        if (v1) {
            float c2 = ctx[nt][2] * inv1, c3 = ctx[nt][3] * inv1;
            float2 fwv = *(const float2*)(fw + (size_t)gl1 * FF + f);
            *(float2*)(ctx_out + cb1 + f) = make_float2(c2, c3);
            y1 += c2 * fwv.x + c3 * fwv.y;
        }
    }
    y0 += __shfl_xor_sync(0xffffffffu, y0, 1);
    y0 += __shfl_xor_sync(0xffffffffu, y0, 2);
    y1 += __shfl_xor_sync(0xffffffffu, y1, 1);
    y1 += __shfl_xor_sync(0xffffffffu, y1, 2);
    if (q == 0 && v0) y_out[(size_t)b * LL + gl0] = y0 + fb[gl0];
    if (q == 0 && v1) y_out[(size_t)b * LL + gl1] = y1 + fb[gl1];
}

// ---------------- launch ----------------
extern "C" void kernel_launch(void* const* d_in, const int* in_sizes, int n_in,
                              void* d_out, int out_size) {
    const int*   docs  = (const int*)  d_in[0];
    const int*   leaf  = (const int*)  d_in[3];
    const float* embed = (const float*)d_in[4];
    const float* wu    = (const float*)d_in[5];
    const float* fw    = (const float*)d_in[6];
    const float* fb    = (const float*)d_in[7];
    const float* w3    = (const float*)d_in[8];
    const float* b3    = (const float*)d_in[9];
    const float* w5    = (const float*)d_in[10];
    const float* b5    = (const float*)d_in[11];
    const float* w9    = (const float*)d_in[12];
    const float* b9    = (const float*)d_in[13];

    const long long NY = (long long)BB * LL;
    const long long NC = (long long)BB * LL * FF;
    float* out = (float*)d_out;
    float* d_y;
    float* d_ctx;
    if ((long long)out_size == NY + NC) {
        d_y = out; d_ctx = out + NY;
    } else if ((long long)out_size == NC) {
        d_ctx = out;
        cudaGetSymbolAddress((void**)&d_y, g_y_fb);
    } else if ((long long)out_size == NY) {
        d_y = out;
        cudaGetSymbolAddress((void**)&d_ctx, g_ctx_fb);
    } else {
        d_y = out; d_ctx = out + NY;
    }

    float* wp3; float* wp5; float* wp9;
    cudaGetSymbolAddress((void**)&wp3, g_wp3);
    cudaGetSymbolAddress((void**)&wp5, g_wp5);
    cudaGetSymbolAddress((void**)&wp9, g_wp9);

    repack_kernel<<<(3 * EE * FF + 255) / 256, 256>>>(w3, wp3, 3);
    repack_kernel<<<(5 * EE * FF + 255) / 256, 256>>>(w5, wp5, 5);
    repack_kernel<<<(9 * EE * FF + 255) / 256, 256>>>(w9, wp9, 9);

    dim3 cgrid((SS + 31) / 32, BB);
    conv_kernel<<<cgrid, 256>>>(docs, embed, b3, b5, b9);

    const int smem_bytes = (LBLK * WU_STRIDE + FF * X_STRIDE + 4 * 16 * P_STRIDE) * 4;
    cudaFuncSetAttribute((const void*)attn_tc_kernel,
                         cudaFuncAttributeMaxDynamicSharedMemorySize, smem_bytes);
    dim3 agrid((LL + LBLK - 1) / LBLK, BB);
    attn_tc_kernel<<<agrid, 128, smem_bytes>>>(wu, leaf, fw, fb, d_y, d_ctx);
}

// round 6
// speedup vs baseline: 3.6597x; 1.4260x over previous
#include <cuda_runtime.h>
#include <math.h>
#include <math_constants.h>
#include <stdint.h>

#define BB 8
#define SS 2500
#define EE 128
#define FF 128
#define LL 8921

// ---------------- device scratch (no allocations allowed) ----------------
__device__ __align__(16) float g_wp3[3 * EE * FF];
__device__ __align__(16) float g_wp5[5 * EE * FF];
__device__ __align__(16) float g_wp9[9 * EE * FF];
// +64 pad: bulk/cp.async tile loads over-read row tails; pad keeps them in-bounds
__device__ __align__(16) float g_wf[(size_t)BB * FF * SS + 64];
__device__ float g_y_fb[BB * LL];
__device__ float g_ctx_fb[(size_t)BB * LL * FF];

// ---------------- weight repack: [F][E][K] -> [K][E][F] ----------------
__global__ void repack_kernel(const float* __restrict__ src,
                              float* __restrict__ dst, int K) {
    int idx = blockIdx.x * blockDim.x + threadIdx.x;
    int total = K * EE * FF;
    if (idx >= total) return;
    int kk = idx / (EE * FF);
    int r  = idx % (EE * FF);
    int e  = r / FF;
    int f  = r % FF;
    dst[idx] = src[(f * EE + e) * K + kk];
}

// ================= conv v2: 4f x 8s per thread, register xs window =================
#define CTILE 64
#define XSTR  72

template <int K>
__device__ __forceinline__ void conv_max2(const float* __restrict__ wp,
                                          const float* __restrict__ bias,
                                          const float (*xs)[XSTR],
                                          int f0, int sg, float mx[4][8]) {
    float acc[4][8];
#pragma unroll
    for (int i = 0; i < 4; i++)
#pragma unroll
        for (int j = 0; j < 8; j++) acc[i][j] = 0.f;

    const int P = K / 2;
    const int w0 = 8 * sg;           // window start (word, 16B aligned)
#pragma unroll 2
    for (int e = 0; e < EE; e++) {
        float xw[16];
        const float4* xr = (const float4*)(&xs[e][w0]);
        float4 xa = xr[0], xb = xr[1], xc = xr[2], xd = xr[3];
        xw[0]=xa.x; xw[1]=xa.y; xw[2]=xa.z; xw[3]=xa.w;
        xw[4]=xb.x; xw[5]=xb.y; xw[6]=xb.z; xw[7]=xb.w;
        xw[8]=xc.x; xw[9]=xc.y; xw[10]=xc.z; xw[11]=xc.w;
        xw[12]=xd.x; xw[13]=xd.y; xw[14]=xd.z; xw[15]=xd.w;
#pragma unroll
        for (int kk = 0; kk < K; kk++) {
            float4 wv = *(const float4*)(wp + (kk * EE + e) * FF + f0);
            const int off = 4 + kk - P;
#pragma unroll
            for (int j = 0; j < 8; j++) {
                float x = xw[off + j];
                acc[0][j] += wv.x * x;
                acc[1][j] += wv.y * x;
                acc[2][j] += wv.z * x;
                acc[3][j] += wv.w * x;
            }
        }
    }
#pragma unroll
    for (int i = 0; i < 4; i++) {
        float bi = bias[f0 + i];
#pragma unroll
        for (int j = 0; j < 8; j++)
            mx[i][j] = fmaxf(mx[i][j], tanhf(acc[i][j] + bi));
    }
}

__global__ __launch_bounds__(256, 2) void conv_kernel(
    const int* __restrict__ docs, const float* __restrict__ embed,
    const float* __restrict__ b3, const float* __restrict__ b5,
    const float* __restrict__ b9) {
    __shared__ float xs[EE][XSTR];   // positions s0-4 .. s0+67

    int b  = blockIdx.y;
    int s0 = blockIdx.x * CTILE;
    int tid = threadIdx.x, w = tid >> 5, lane = tid & 31;

    // gather 72 embedding rows: warp w handles 9 positions
#pragma unroll
    for (int q = 0; q < 9; q++) {
        int p = w * 9 + q;
        int s = s0 - 4 + p;
        if (s >= 0 && s < SS) {
            int tok = docs[b * SS + s];
            const float* er = embed + (size_t)tok * EE;
            xs[lane      ][p] = er[lane];
            xs[lane + 32][p] = er[lane + 32];
            xs[lane + 64][p] = er[lane + 64];
            xs[lane + 96][p] = er[lane + 96];
        } else {
            xs[lane][p] = 0.f; xs[lane + 32][p] = 0.f;
            xs[lane + 64][p] = 0.f; xs[lane + 96][p] = 0.f;
        }
    }
    __syncthreads();

    int fg = tid >> 3;          // 0..31 -> f0 = 4*fg
    int sg = tid & 7;           // 0..7  -> s = s0 + 8*sg + j
    int f0 = fg * 4;

    float mx[4][8];
#pragma unroll
    for (int i = 0; i < 4; i++)
#pragma unroll
        for (int j = 0; j < 8; j++) mx[i][j] = -1e30f;

    conv_max2<3>(g_wp3, b3, xs, f0, sg, mx);
    conv_max2<5>(g_wp5, b5, xs, f0, sg, mx);
    conv_max2<9>(g_wp9, b9, xs, f0, sg, mx);

#pragma unroll
    for (int i = 0; i < 4; i++) {
        float* orow = g_wf + ((size_t)b * FF + f0 + i) * SS;
#pragma unroll
        for (int j = 0; j < 8; j++) {
            int s = s0 + 8 * sg + j;
            if (s < SS) orow[s] = mx[i][j];
        }
    }
}

// ================= tensor-core label attention v2 =================
// 128 threads (4 warps), warp owns 16 labels. WU fragments live in registers
// for the whole S loop. X tile double-buffered via cp.async.

#define LBLK 64
#define X_STRIDE  36
#define P_STRIDE  36
#define NT_TILES  ((SS + 31) / 32)   // 79

__device__ __forceinline__ uint32_t f2tf32(float v) {
    uint32_t t;
    asm("cvt.rna.tf32.f32 %0, %1;" : "=r"(t) : "f"(v));
    return t;
}

__device__ __forceinline__ void mma_tf32(float (&d)[4],
                                         uint32_t a0, uint32_t a1,
                                         uint32_t a2, uint32_t a3,
                                         uint32_t b0, uint32_t b1) {
    asm volatile(
        "mma.sync.aligned.m16n8k8.row.col.f32.tf32.tf32.f32 "
        "{%0,%1,%2,%3}, {%4,%5,%6,%7}, {%8,%9}, {%0,%1,%2,%3};"
        : "+f"(d[0]), "+f"(d[1]), "+f"(d[2]), "+f"(d[3])
        : "r"(a0), "r"(a1), "r"(a2), "r"(a3), "r"(b0), "r"(b1));
}

__device__ __forceinline__ void ldx_async(float* s_buf, const float* wfb,
                                          int s0, int tid) {
#pragma unroll
    for (int v = 0; v < 8; v++) {
        int lin = v * 128 + tid;
        int f = lin >> 3, c = lin & 7;
        uint32_t dst = (uint32_t)__cvta_generic_to_shared(s_buf + f * X_STRIDE + c * 4);
        const float* src = wfb + (size_t)f * SS + s0 + c * 4;
        asm volatile("cp.async.ca.shared.global [%0], [%1], 16;"
                     :: "r"(dst), "l"(src));
    }
}

__global__ __launch_bounds__(128, 2) void attn_tc_kernel(
    const float* __restrict__ wu_w, const int* __restrict__ leaf,
    const float* __restrict__ fw, const float* __restrict__ fb,
    float* __restrict__ y_out, float* __restrict__ ctx_out) {
    extern __shared__ float sm[];
    float* s_x0 = sm;                               // [128][36]
    float* s_x1 = sm + FF * X_STRIDE;               // [128][36]
    float* s_p  = s_x1 + FF * X_STRIDE;             // [4][16][36]

    int b   = blockIdx.y;
    int l0  = blockIdx.x * LBLK;
    int tid = threadIdx.x;
    int wid = tid >> 5, lane = tid & 31;
    int q = lane & 3;        // k/col group
    int r = lane >> 2;       // row group

    const int lrow = 16 * wid + r;
    int gl0 = l0 + lrow, gl1 = gl0 + 8;
    bool v0 = gl0 < LL, v1 = gl1 < LL;

    // WU A-fragments in registers for the whole loop (64 regs)
    const float* wr0 = wu_w + (size_t)(v0 ? leaf[gl0] : 0) * FF;
    const float* wr1 = wu_w + (size_t)(v1 ? leaf[gl1] : 0) * FF;
    uint32_t wua[16][4];
#pragma unroll
    for (int k = 0; k < 16; k++) {
        wua[k][0] = v0 ? f2tf32(wr0[8 * k + q])     : 0u;
        wua[k][1] = v1 ? f2tf32(wr1[8 * k + q])     : 0u;
        wua[k][2] = v0 ? f2tf32(wr0[8 * k + q + 4]) : 0u;
        wua[k][3] = v1 ? f2tf32(wr1[8 * k + q + 4]) : 0u;
    }

    const float* wfb = g_wf + (size_t)b * FF * SS;
    float* s_pw = s_p + wid * 16 * P_STRIDE;

    float ctx[16][4];
#pragma unroll
    for (int nt = 0; nt < 16; nt++)
#pragma unroll
        for (int c = 0; c < 4; c++) ctx[nt][c] = 0.f;

    float m0 = -CUDART_INF_F, m1 = -CUDART_INF_F;
    float se0 = 0.f, se1 = 0.f;

    ldx_async(s_x0, wfb, 0, tid);
    asm volatile("cp.async.commit_group;");

    for (int t = 0; t < NT_TILES; t++) {
        int s0 = t * 32;
        float* xb = (t & 1) ? s_x1 : s_x0;
        if (t + 1 < NT_TILES) {
            ldx_async((t & 1) ? s_x0 : s_x1, wfb, s0 + 32, tid);
            asm volatile("cp.async.commit_group;");
            asm volatile("cp.async.wait_group 1;");
        } else {
            asm volatile("cp.async.wait_group 0;");
        }
        __syncthreads();

        // ---- GEMM1: scores ----
        float sc[4][4];
#pragma unroll
        for (int nt = 0; nt < 4; nt++)
#pragma unroll
            for (int c = 0; c < 4; c++) sc[nt][c] = 0.f;

#pragma unroll 4
        for (int k = 0; k < 16; k++) {
            int k0 = 8 * k;
#pragma unroll
            for (int nt = 0; nt < 4; nt++) {
                uint32_t b0 = __float_as_uint(xb[(k0 + q) * X_STRIDE + 8 * nt + r]);
                uint32_t b1 = __float_as_uint(xb[(k0 + q + 4) * X_STRIDE + 8 * nt + r]);
                mma_tf32(sc[nt], wua[k][0], wua[k][1], wua[k][2], wua[k][3], b0, b1);
            }
        }

        // ---- mask tail columns ----
#pragma unroll
        for (int nt = 0; nt < 4; nt++) {
            int s_even = s0 + 8 * nt + 2 * q;
            if (s_even >= SS)     { sc[nt][0] = -CUDART_INF_F; sc[nt][2] = -CUDART_INF_F; }
            if (s_even + 1 >= SS) { sc[nt][1] = -CUDART_INF_F; sc[nt][3] = -CUDART_INF_F; }
        }

        // ---- online softmax ----
        float mx0 = -CUDART_INF_F, mx1 = -CUDART_INF_F;
#pragma unroll
        for (int nt = 0; nt < 4; nt++) {
            mx0 = fmaxf(mx0, fmaxf(sc[nt][0], sc[nt][1]));
            mx1 = fmaxf(mx1, fmaxf(sc[nt][2], sc[nt][3]));
        }
        mx0 = fmaxf(mx0, __shfl_xor_sync(0xffffffffu, mx0, 1));
        mx0 = fmaxf(mx0, __shfl_xor_sync(0xffffffffu, mx0, 2));
        mx1 = fmaxf(mx1, __shfl_xor_sync(0xffffffffu, mx1, 1));
        mx1 = fmaxf(mx1, __shfl_xor_sync(0xffffffffu, mx1, 2));

        float nm0 = fmaxf(m0, mx0), nm1 = fmaxf(m1, mx1);
        float scale0 = __expf(m0 - nm0), scale1 = __expf(m1 - nm1);
        m0 = nm0; m1 = nm1;

        float sum0 = 0.f, sum1 = 0.f;
#pragma unroll
        for (int nt = 0; nt < 4; nt++) {
            float p0 = __expf(sc[nt][0] - m0);
            float p1 = __expf(sc[nt][1] - m0);
            float p2 = __expf(sc[nt][2] - m1);
            float p3 = __expf(sc[nt][3] - m1);
            sum0 += p0 + p1;
            sum1 += p2 + p3;
            int col = 8 * nt + 2 * q;
            s_pw[r * P_STRIDE + col]           = p0;
            s_pw[r * P_STRIDE + col + 1]       = p1;
            s_pw[(r + 8) * P_STRIDE + col]     = p2;
            s_pw[(r + 8) * P_STRIDE + col + 1] = p3;
        }
        sum0 += __shfl_xor_sync(0xffffffffu, sum0, 1);
        sum0 += __shfl_xor_sync(0xffffffffu, sum0, 2);
        sum1 += __shfl_xor_sync(0xffffffffu, sum1, 1);
        sum1 += __shfl_xor_sync(0xffffffffu, sum1, 2);
        se0 = se0 * scale0 + sum0;
        se1 = se1 * scale1 + sum1;

#pragma unroll
        for (int nt = 0; nt < 16; nt++) {
            ctx[nt][0] *= scale0; ctx[nt][1] *= scale0;
            ctx[nt][2] *= scale1; ctx[nt][3] *= scale1;
        }
        __syncwarp();

        // ---- GEMM2: ctx += P @ X^T ----
#pragma unroll
        for (int k = 0; k < 4; k++) {
            int k0 = 8 * k;
            uint32_t a0 = __float_as_uint(s_pw[r * P_STRIDE + k0 + q]);
            uint32_t a1 = __float_as_uint(s_pw[(r + 8) * P_STRIDE + k0 + q]);
            uint32_t a2 = __float_as_uint(s_pw[r * P_STRIDE + k0 + q + 4]);
            uint32_t a3 = __float_as_uint(s_pw[(r + 8) * P_STRIDE + k0 + q + 4]);
#pragma unroll
            for (int nt = 0; nt < 16; nt++) {
                uint32_t b0 = __float_as_uint(xb[(8 * nt + r) * X_STRIDE + k0 + q]);
                uint32_t b1 = __float_as_uint(xb[(8 * nt + r) * X_STRIDE + k0 + q + 4]);
                mma_tf32(ctx[nt], a0, a1, a2, a3, b0, b1);
            }
        }
        __syncthreads();
    }

    // ---- epilogue ----
    float inv0 = 1.f / se0, inv1 = 1.f / se1;
    size_t cb0 = ((size_t)b * LL + gl0) * FF;
    size_t cb1 = ((size_t)b * LL + gl1) * FF;
    float y0 = 0.f, y1 = 0.f;
#pragma unroll
    for (int nt = 0; nt < 16; nt++) {
        int f = 8 * nt + 2 * q;
        if (v0) {
            float c0 = ctx[nt][0] * inv0, c1 = ctx[nt][1] * inv0;
            float2 fwv = *(const float2*)(fw + (size_t)gl0 * FF + f);
            *(float2*)(ctx_out + cb0 + f) = make_float2(c0, c1);
            y0 += c0 * fwv.x + c1 * fwv.y;
        }
        if (v1) {
            float c2 = ctx[nt][2] * inv1, c3 = ctx[nt][3] * inv1;
            float2 fwv = *(const float2*)(fw + (size_t)gl1 * FF + f);
            *(float2*)(ctx_out + cb1 + f) = make_float2(c2, c3);
            y1 += c2 * fwv.x + c3 * fwv.y;
        }
    }
    y0 += __shfl_xor_sync(0xffffffffu, y0, 1);
    y0 += __shfl_xor_sync(0xffffffffu, y0, 2);
    y1 += __shfl_xor_sync(0xffffffffu, y1, 1);
    y1 += __shfl_xor_sync(0xffffffffu, y1, 2);
    if (q == 0 && v0) y_out[(size_t)b * LL + gl0] = y0 + fb[gl0];
    if (q == 0 && v1) y_out[(size_t)b * LL + gl1] = y1 + fb[gl1];
}

// ---------------- launch ----------------
extern "C" void kernel_launch(void* const* d_in, const int* in_sizes, int n_in,
                              void* d_out, int out_size) {
    const int*   docs  = (const int*)  d_in[0];
    const int*   leaf  = (const int*)  d_in[3];
    const float* embed = (const float*)d_in[4];
    const float* wu    = (const float*)d_in[5];
    const float* fw    = (const float*)d_in[6];
    const float* fb    = (const float*)d_in[7];
    const float* w3    = (const float*)d_in[8];
    const float* b3    = (const float*)d_in[9];
    const float* w5    = (const float*)d_in[10];
    const float* b5    = (const float*)d_in[11];
    const float* w9    = (const float*)d_in[12];
    const float* b9    = (const float*)d_in[13];

    const long long NY = (long long)BB * LL;
    const long long NC = (long long)BB * LL * FF;
    float* out = (float*)d_out;
    float* d_y;
    float* d_ctx;
    if ((long long)out_size == NY + NC) {
        d_y = out; d_ctx = out + NY;
    } else if ((long long)out_size == NC) {
        d_ctx = out;
        cudaGetSymbolAddress((void**)&d_y, g_y_fb);
    } else if ((long long)out_size == NY) {
        d_y = out;
        cudaGetSymbolAddress((void**)&d_ctx, g_ctx_fb);
    } else {
        d_y = out; d_ctx = out + NY;
    }

    float* wp3; float* wp5; float* wp9;
    cudaGetSymbolAddress((void**)&wp3, g_wp3);
    cudaGetSymbolAddress((void**)&wp5, g_wp5);
    cudaGetSymbolAddress((void**)&wp9, g_wp9);

    repack_kernel<<<(3 * EE * FF + 255) / 256, 256>>>(w3, wp3, 3);
    repack_kernel<<<(5 * EE * FF + 255) / 256, 256>>>(w5, wp5, 5);
    repack_kernel<<<(9 * EE * FF + 255) / 256, 256>>>(w9, wp9, 9);

    dim3 cgrid((SS + CTILE - 1) / CTILE, BB);
    conv_kernel<<<cgrid, 256>>>(docs, embed, b3, b5, b9);

    const int smem_bytes = (2 * FF * X_STRIDE + 4 * 16 * P_STRIDE) * 4;
    cudaFuncSetAttribute((const void*)attn_tc_kernel,
                         cudaFuncAttributeMaxDynamicSharedMemorySize, smem_bytes);
    dim3 agrid((LL + LBLK - 1) / LBLK, BB);
    attn_tc_kernel<<<agrid, 128, smem_bytes>>>(wu, leaf, fw, fb, d_y, d_ctx);
}